// round 11
// baseline (speedup 1.0000x reference)
#include <cuda_runtime.h>
#include <cuda_fp16.h>
#include <cstdint>
#include <cstddef>

// Problem constants
#define BB     4
#define NTOK   2048
#define DMODEL 1024
#define NH     16
#define HD     64
#define D3     (3 * DMODEL)    // 3072
#define MROWS  (BB * NTOK)     // 8192
#define SCALE  0.125f          // 1/sqrt(64)

// Scratch (static device globals — allocation-free). All operands pre-split
// into fp16 (hi, lo) pairs so hot loops do zero conversion work.
__device__ __half g_x_h[(size_t)MROWS * DMODEL];
__device__ __half g_x_l[(size_t)MROWS * DMODEL];
__device__ __half g_wqkvT_h[(size_t)D3 * DMODEL];
__device__ __half g_wqkvT_l[(size_t)D3 * DMODEL];
__device__ __half g_woutT_h[(size_t)DMODEL * DMODEL];
__device__ __half g_woutT_l[(size_t)DMODEL * DMODEL];
__device__ __half g_qkv_h[(size_t)MROWS * D3];
__device__ __half g_qkv_l[(size_t)MROWS * D3];
__device__ __half g_att_h[(size_t)MROWS * DMODEL];
__device__ __half g_att_l[(size_t)MROWS * DMODEL];

// ---------------------------------------------------------------------------
// Helpers (sm_80-era PTX only: mma.sync / ldmatrix / cp.async)
// ---------------------------------------------------------------------------
__device__ __forceinline__ void split2(float a, float b, uint32_t& hi, uint32_t& lo) {
    __half2 h = __floats2half2_rn(a, b);
    float2 hf = __half22float2(h);
    __half2 l = __floats2half2_rn(a - hf.x, b - hf.y);
    hi = *reinterpret_cast<uint32_t*>(&h);
    lo = *reinterpret_cast<uint32_t*>(&l);
}
__device__ __forceinline__ uint32_t smem_u32(const void* p) {
    uint32_t a;
    asm("{ .reg .u64 t; cvta.to.shared.u64 t, %1; cvt.u32.u64 %0, t; }"
        : "=r"(a) : "l"(p));
    return a;
}
__device__ __forceinline__ void cp16(uint32_t dst, const void* src) {
    asm volatile("cp.async.cg.shared.global [%0], [%1], 16;"
                 :: "r"(dst), "l"(src));
}
#define CP_COMMIT() asm volatile("cp.async.commit_group;" ::: "memory")
#define CP_WAIT0()  asm volatile("cp.async.wait_group 0;" ::: "memory")
#define CP_WAIT1()  asm volatile("cp.async.wait_group 1;" ::: "memory")

#define MMA_F16(d, a0, a1, a2, a3, b0, b1)                                     \
    asm volatile(                                                              \
        "mma.sync.aligned.m16n8k16.row.col.f32.f16.f16.f32 "                   \
        "{%0,%1,%2,%3},{%4,%5,%6,%7},{%8,%9},{%0,%1,%2,%3};"                   \
        : "+f"((d)[0]), "+f"((d)[1]), "+f"((d)[2]), "+f"((d)[3])               \
        : "r"(a0), "r"(a1), "r"(a2), "r"(a3), "r"(b0), "r"(b1))

#define LDSM_X4(R0, R1, R2, R3, ADDR)                                          \
    asm volatile("ldmatrix.sync.aligned.m8n8.x4.shared.b16 {%0,%1,%2,%3},[%4];"\
                 : "=r"(R0), "=r"(R1), "=r"(R2), "=r"(R3) : "r"(ADDR))
#define LDSM_X4T(R0, R1, R2, R3, ADDR)                                         \
    asm volatile("ldmatrix.sync.aligned.m8n8.x4.trans.shared.b16 "             \
                 "{%0,%1,%2,%3},[%4];"                                         \
                 : "=r"(R0), "=r"(R1), "=r"(R2), "=r"(R3) : "r"(ADDR))

// ---------------------------------------------------------------------------
// Pre-pass kernels
// ---------------------------------------------------------------------------
__global__ __launch_bounds__(256) void split_kernel(
    const float* __restrict__ in, __half* __restrict__ oh,
    __half* __restrict__ ol, int n4)
{
    int i = blockIdx.x * 256 + threadIdx.x;
    if (i >= n4) return;
    float4 v = *(const float4*)(in + (size_t)i * 4);
    uint32_t h0, l0, h1, l1;
    split2(v.x, v.y, h0, l0);
    split2(v.z, v.w, h1, l1);
    *(uint2*)(oh + (size_t)i * 4) = make_uint2(h0, h1);
    *(uint2*)(ol + (size_t)i * 4) = make_uint2(l0, l1);
}

// out[C][R] = split(in[R][C])
__global__ __launch_bounds__(256) void transpose_split_kernel(
    const float* __restrict__ in, __half* __restrict__ oh,
    __half* __restrict__ ol, int R, int Cc)
{
    __shared__ float tile[32][33];
    int c0 = blockIdx.x * 32, r0 = blockIdx.y * 32;
    int lx = threadIdx.x & 31, ly = threadIdx.x >> 5;
#pragma unroll
    for (int rr = ly; rr < 32; rr += 8)
        tile[rr][lx] = in[(size_t)(r0 + rr) * Cc + c0 + lx];
    __syncthreads();
#pragma unroll
    for (int rr = ly; rr < 32; rr += 8) {
        float v = tile[lx][rr];
        __half h = __float2half_rn(v);
        __half l = __float2half_rn(v - __half2float(h));
        oh[(size_t)(c0 + rr) * R + r0 + lx] = h;
        ol[(size_t)(c0 + rr) * R + r0 + lx] = l;
    }
}

// ---------------------------------------------------------------------------
// fp16x3 GEMM (pre-split operands): C = A@BT^T + bias
// BM=128, BN=128, BK=32 halves; 128 threads, 4 warps in 2x2; warp tile
// 64x64 (CUTLASS-style). 2 CTAs/SM -> 255-reg budget; each B-frag feeds 4
// m-tiles (MMA:LDSM 6:1). 3-stage cp.async pipeline, one barrier per tile.
// Smem rows: 32 halves = 4 chunks x 16B, chunk XOR (row&3). ldmatrix frags.
// ---------------------------------------------------------------------------
#define G_BUF 32768   // bytes per pipeline stage (4 regions x 8KB)

template<bool SPLIT_OUT>
__global__ __launch_bounds__(128, 2) void gemm_h2_kernel(
    const __half* __restrict__ Ah, const __half* __restrict__ Al,
    const __half* __restrict__ Bh, const __half* __restrict__ Bl,
    const float* __restrict__ bias,
    float* __restrict__ Cf, __half* __restrict__ Ch, __half* __restrict__ Cl,
    int M, int Nn, int K)
{
    extern __shared__ char smc[];
    const uint32_t sb = smem_u32(smc);

    const int t    = threadIdx.x;
    const int lane = t & 31, wid = t >> 5;
    const int g    = lane >> 2, tg = lane & 3;
    const int wm   = wid >> 1, wn = wid & 1;       // 2x2 warp grid, 64x64 tiles
    const int m0   = blockIdx.y * 128;
    const int n0   = blockIdx.x * 128;

    // gmem->smem: per region, thread t loads row t (all 4 chunks)
    const __half* __restrict__ arrs[4] = {Ah, Al, Bh, Bl};
    const int rowb[4] = {m0, m0, n0, n0};

    // ldmatrix address components (region-relative rows)
    int arow[4];
#pragma unroll
    for (int mt = 0; mt < 4; mt++) arow[mt] = wm * 64 + mt * 16 + (lane & 15);
    const int acb = lane >> 4;                 // chunk bit from lane
    int brow[4];
#pragma unroll
    for (int p = 0; p < 4; p++)
        brow[p] = wn * 64 + p * 16 + ((lane >> 4) << 3) + (lane & 7);
    const int bcb = (lane >> 3) & 1;

    float acc[4][8][4];
#pragma unroll
    for (int mt = 0; mt < 4; mt++)
#pragma unroll
        for (int nt = 0; nt < 8; nt++)
#pragma unroll
            for (int i = 0; i < 4; i++) acc[mt][nt][i] = 0.0f;

    const int NT = K / 32;

    // issue tile kt into pipeline stage ss (16 cp16 per thread)
    auto issue = [&](int kt, int ss) {
#pragma unroll
        for (int r = 0; r < 4; r++) {
#pragma unroll
            for (int ch = 0; ch < 4; ch++) {
                const __half* src = arrs[r] +
                    (size_t)(rowb[r] + t) * K + kt * 32 + ch * 8;
                uint32_t dst = sb + ss * G_BUF + r * 8192 +
                    (t * 4 + (ch ^ (t & 3))) * 16;
                cp16(dst, src);
            }
        }
        CP_COMMIT();
    };

    issue(0, 0);
    issue(1, 1);

    int stage = 0;
    for (int kt = 0; kt < NT; kt++) {
        if (kt + 1 < NT) CP_WAIT1(); else CP_WAIT0();
        __syncthreads();   // also guards stage reuse: all warps done with kt-1
        if (kt + 2 < NT) {
            int ns = stage + 2; if (ns >= 3) ns -= 3;
            issue(kt + 2, ns);
        }

        const uint32_t bufb = sb + stage * G_BUF;
#pragma unroll
        for (int kc = 0; kc < 2; kc++) {
            uint32_t ah[4][4], al[4][4];
#pragma unroll
            for (int mt = 0; mt < 4; mt++) {
                int ch = kc * 2 + acb;
                uint32_t ad = bufb + (arow[mt] * 4 + (ch ^ (arow[mt] & 3))) * 16;
                LDSM_X4(ah[mt][0], ah[mt][1], ah[mt][2], ah[mt][3], ad);
                LDSM_X4(al[mt][0], al[mt][1], al[mt][2], al[mt][3], ad + 8192);
            }
#pragma unroll
            for (int p = 0; p < 4; p++) {
                int ch = kc * 2 + bcb;
                uint32_t bd = bufb + 16384 +
                    (brow[p] * 4 + (ch ^ (brow[p] & 3))) * 16;
                uint32_t bh[4], bl[4];
                LDSM_X4(bh[0], bh[1], bh[2], bh[3], bd);
                LDSM_X4(bl[0], bl[1], bl[2], bl[3], bd + 8192);
#pragma unroll
                for (int e = 0; e < 2; e++) {
                    uint32_t bh0 = e ? bh[2] : bh[0], bh1 = e ? bh[3] : bh[1];
                    uint32_t bl0 = e ? bl[2] : bl[0], bl1 = e ? bl[3] : bl[1];
#pragma unroll
                    for (int mt = 0; mt < 4; mt++) {
                        float* d = acc[mt][2 * p + e];
                        MMA_F16(d, ah[mt][0], ah[mt][1], ah[mt][2], ah[mt][3], bh0, bh1);
                        MMA_F16(d, ah[mt][0], ah[mt][1], ah[mt][2], ah[mt][3], bl0, bl1);
                        MMA_F16(d, al[mt][0], al[mt][1], al[mt][2], al[mt][3], bh0, bh1);
                    }
                }
            }
        }
        if (++stage == 3) stage = 0;
    }

    // epilogue
#pragma unroll
    for (int mt = 0; mt < 4; mt++) {
        int r0 = m0 + wm * 64 + mt * 16 + g;
#pragma unroll
        for (int nt = 0; nt < 8; nt++) {
            int cc = n0 + wn * 64 + nt * 8 + tg * 2;
            float2 bv = *(const float2*)(bias + cc);
            float* d = acc[mt][nt];
            float v0 = d[0] + bv.x, v1 = d[1] + bv.y;
            float v2 = d[2] + bv.x, v3 = d[3] + bv.y;
            if (SPLIT_OUT) {
                uint32_t h, l;
                split2(v0, v1, h, l);
                *(uint32_t*)(Ch + (size_t)r0 * Nn + cc) = h;
                *(uint32_t*)(Cl + (size_t)r0 * Nn + cc) = l;
                split2(v2, v3, h, l);
                *(uint32_t*)(Ch + (size_t)(r0 + 8) * Nn + cc) = h;
                *(uint32_t*)(Cl + (size_t)(r0 + 8) * Nn + cc) = l;
            } else {
                *(float2*)(Cf + (size_t)r0 * Nn + cc) = make_float2(v0, v1);
                *(float2*)(Cf + (size_t)(r0 + 8) * Nn + cc) = make_float2(v2, v3);
            }
        }
    }
}

// ---------------------------------------------------------------------------
// Flash attention, fp16x3, pre-split inputs, ldmatrix fragments.
// CTA = 128 q-rows x one (b,h); 8 warps, each 16 q-rows. K/V double-buffered.
// One barrier per tile (top-of-loop sync covers buffer reuse).
// Smem rows: 64 halves = 8 chunks x 16B, chunk XOR (row&7).
// Layout: Qh 0 | Ql 16K | buf0 {Kh,Kl,Vh,Vl @8K} 32K | buf1 64K. Total 96K.
// ---------------------------------------------------------------------------
#define ATT_SMEM 98304
#define AKV_BASE 32768

__global__ __launch_bounds__(256) void attn_h2_kernel(
    const __half* __restrict__ qh, const __half* __restrict__ ql,
    __half* __restrict__ oh, __half* __restrict__ ol)
{
    extern __shared__ char smc[];
    const uint32_t sb = smem_u32(smc);

    const int t    = threadIdx.x;
    const int lane = t & 31, wid = t >> 5;
    const int g    = lane >> 2, tg = lane & 3;
    const int q0   = blockIdx.x * 128;
    const int h    = blockIdx.y;
    const int b    = blockIdx.z;
    const size_t rowbase = (size_t)b * NTOK;

    // ldmatrix row components
    const int qrow = wid * 16 + (lane & 15);     // A-frag rows (fixed per thread)
    const int qcb  = lane >> 4;
    const int krow[4] = {                        // K B-frag rows per octet-pair
        0  + ((lane >> 4) << 3) + (lane & 7),
        16 + ((lane >> 4) << 3) + (lane & 7),
        32 + ((lane >> 4) << 3) + (lane & 7),
        48 + ((lane >> 4) << 3) + (lane & 7)};
    const int kcb = (lane >> 3) & 1;
    const int vrow[2] = {                        // V .trans rows per s-group
        ( (lane >> 4)      ) * 16 + (((lane >> 3) & 1) << 3) + (lane & 7),
        ( (lane >> 4) + 2  ) * 16 + (((lane >> 3) & 1) << 3) + (lane & 7)};

    // ---- issue Q (16 cp/thread) + KV tile 0 (committed together) ----
    {
#pragma unroll
        for (int hl = 0; hl < 2; hl++) {
            const __half* arr = hl ? ql : qh;
#pragma unroll
            for (int j = 0; j < 4; j++) {
                int id = t * 4 + j, row = id >> 3, ch = id & 7;
                const __half* src = arr + (rowbase + q0 + row) * D3 + h * 64 + ch * 8;
                uint32_t dst = sb + hl * 16384 + (row * 8 + (ch ^ (row & 7))) * 16;
                cp16(dst, src);
            }
        }
    }
    auto issue_kv = [&](int kt, int bb) {
        const int k0 = kt * 64;
#pragma unroll
        for (int r = 0; r < 4; r++) {
            const __half* arr = (r & 1) ? ql : qh;
            const int colb = ((r >> 1) ? 2 * DMODEL : DMODEL) + h * 64;
#pragma unroll
            for (int j = 0; j < 2; j++) {
                int id = t * 2 + j, row = id >> 3, ch = id & 7;
                const __half* src = arr + (rowbase + k0 + row) * D3 + colb + ch * 8;
                uint32_t dst = sb + AKV_BASE + bb * 32768 + r * 8192 +
                               (row * 8 + (ch ^ (row & 7))) * 16;
                cp16(dst, src);
            }
        }
        CP_COMMIT();
    };
    issue_kv(0, 0);

    float m0f = -1e30f, m1f = -1e30f, l0 = 0.0f, l1 = 0.0f;
    float oacc[8][4];
#pragma unroll
    for (int nt = 0; nt < 8; nt++)
#pragma unroll
        for (int i = 0; i < 4; i++) oacc[nt][i] = 0.0f;

    for (int kt = 0; kt < NTOK / 64; kt++) {
        const int bb = kt & 1;
        CP_WAIT0();
        __syncthreads();   // tile data visible AND all warps done with kt-1
        if (kt + 1 < NTOK / 64) issue_kv(kt + 1, bb ^ 1);

        const uint32_t kvb = sb + AKV_BASE + bb * 32768;

        // ---- S = Q K^T (3-term) ----
        float sacc[8][4];
#pragma unroll
        for (int nt = 0; nt < 8; nt++)
#pragma unroll
            for (int i = 0; i < 4; i++) sacc[nt][i] = 0.0f;

#pragma unroll
        for (int ks = 0; ks < 4; ks++) {
            int qch = ks * 2 + qcb;
            uint32_t qa = sb + (qrow * 8 + (qch ^ (qrow & 7))) * 16;
            uint32_t Qh_[4], Ql_[4];
            LDSM_X4(Qh_[0], Qh_[1], Qh_[2], Qh_[3], qa);
            LDSM_X4(Ql_[0], Ql_[1], Ql_[2], Ql_[3], qa + 16384);
#pragma unroll
            for (int p = 0; p < 4; p++) {
                int kch = ks * 2 + kcb;
                uint32_t ka = kvb + (krow[p] * 8 + (kch ^ (krow[p] & 7))) * 16;
                uint32_t Kh_[4], Kl_[4];
                LDSM_X4(Kh_[0], Kh_[1], Kh_[2], Kh_[3], ka);
                LDSM_X4(Kl_[0], Kl_[1], Kl_[2], Kl_[3], ka + 8192);
#pragma unroll
                for (int e = 0; e < 2; e++) {
                    uint32_t bh0 = e ? Kh_[2] : Kh_[0], bh1 = e ? Kh_[3] : Kh_[1];
                    uint32_t bl0 = e ? Kl_[2] : Kl_[0], bl1 = e ? Kl_[3] : Kl_[1];
                    float* d = sacc[2 * p + e];
                    MMA_F16(d, Qh_[0], Qh_[1], Qh_[2], Qh_[3], bh0, bh1);
                    MMA_F16(d, Qh_[0], Qh_[1], Qh_[2], Qh_[3], bl0, bl1);
                    MMA_F16(d, Ql_[0], Ql_[1], Ql_[2], Ql_[3], bh0, bh1);
                }
            }
        }

        // ---- online softmax ----
        float mx0 = -1e30f, mx1 = -1e30f;
#pragma unroll
        for (int nt = 0; nt < 8; nt++) {
            sacc[nt][0] *= SCALE; sacc[nt][1] *= SCALE;
            sacc[nt][2] *= SCALE; sacc[nt][3] *= SCALE;
            mx0 = fmaxf(mx0, fmaxf(sacc[nt][0], sacc[nt][1]));
            mx1 = fmaxf(mx1, fmaxf(sacc[nt][2], sacc[nt][3]));
        }
        mx0 = fmaxf(mx0, __shfl_xor_sync(0xffffffffu, mx0, 1));
        mx0 = fmaxf(mx0, __shfl_xor_sync(0xffffffffu, mx0, 2));
        mx1 = fmaxf(mx1, __shfl_xor_sync(0xffffffffu, mx1, 1));
        mx1 = fmaxf(mx1, __shfl_xor_sync(0xffffffffu, mx1, 2));
        float mn0 = fmaxf(m0f, mx0), mn1 = fmaxf(m1f, mx1);
        float c0 = __expf(m0f - mn0), c1 = __expf(m1f - mn1);
        m0f = mn0; m1f = mn1;
        float s0 = 0.0f, s1 = 0.0f;
#pragma unroll
        for (int nt = 0; nt < 8; nt++) {
            sacc[nt][0] = __expf(sacc[nt][0] - mn0);
            sacc[nt][1] = __expf(sacc[nt][1] - mn0);
            sacc[nt][2] = __expf(sacc[nt][2] - mn1);
            sacc[nt][3] = __expf(sacc[nt][3] - mn1);
            s0 += sacc[nt][0] + sacc[nt][1];
            s1 += sacc[nt][2] + sacc[nt][3];
        }
        s0 += __shfl_xor_sync(0xffffffffu, s0, 1);
        s0 += __shfl_xor_sync(0xffffffffu, s0, 2);
        s1 += __shfl_xor_sync(0xffffffffu, s1, 1);
        s1 += __shfl_xor_sync(0xffffffffu, s1, 2);
        l0 = l0 * c0 + s0;
        l1 = l1 * c1 + s1;
#pragma unroll
        for (int nt = 0; nt < 8; nt++) {
            oacc[nt][0] *= c0; oacc[nt][1] *= c0;
            oacc[nt][2] *= c1; oacc[nt][3] *= c1;
        }

        // ---- P fragments (registers; S C-frag == PV A-frag layout) ----
        uint32_t ph[4][4], pl[4][4];
#pragma unroll
        for (int s = 0; s < 4; s++) {
            split2(sacc[2 * s][0],     sacc[2 * s][1],     ph[s][0], pl[s][0]);
            split2(sacc[2 * s][2],     sacc[2 * s][3],     ph[s][1], pl[s][1]);
            split2(sacc[2 * s + 1][0], sacc[2 * s + 1][1], ph[s][2], pl[s][2]);
            split2(sacc[2 * s + 1][2], sacc[2 * s + 1][3], ph[s][3], pl[s][3]);
        }

        // ---- O += P V (3-term); V B-frags via ldmatrix.trans ----
#pragma unroll
        for (int nt = 0; nt < 8; nt++) {
            uint32_t vh[2][4], vl[2][4];
#pragma unroll
            for (int sg = 0; sg < 2; sg++) {
                uint32_t va = kvb + 16384 +
                    (vrow[sg] * 8 + (nt ^ (vrow[sg] & 7))) * 16;
                LDSM_X4T(vh[sg][0], vh[sg][1], vh[sg][2], vh[sg][3], va);
                LDSM_X4T(vl[sg][0], vl[sg][1], vl[sg][2], vl[sg][3], va + 8192);
            }
            float* d = oacc[nt];
#pragma unroll
            for (int s = 0; s < 4; s++) {
                int sg = s >> 1, o = (s & 1) * 2;
                MMA_F16(d, ph[s][0], ph[s][1], ph[s][2], ph[s][3],
                        vh[sg][o], vh[sg][o + 1]);
                MMA_F16(d, ph[s][0], ph[s][1], ph[s][2], ph[s][3],
                        vl[sg][o], vl[sg][o + 1]);
                MMA_F16(d, pl[s][0], pl[s][1], pl[s][2], pl[s][3],
                        vh[sg][o], vh[sg][o + 1]);
            }
        }
    }

    // ---- epilogue: normalize, split to hi/lo halves ----
    float inv0 = 1.0f / l0, inv1 = 1.0f / l1;
    int r0 = q0 + wid * 16 + g;
#pragma unroll
    for (int nt = 0; nt < 8; nt++) {
        int cc = h * HD + nt * 8 + tg * 2;
        uint32_t hh, ll;
        split2(oacc[nt][0] * inv0, oacc[nt][1] * inv0, hh, ll);
        *(uint32_t*)(oh + (rowbase + r0) * DMODEL + cc) = hh;
        *(uint32_t*)(ol + (rowbase + r0) * DMODEL + cc) = ll;
        split2(oacc[nt][2] * inv1, oacc[nt][3] * inv1, hh, ll);
        *(uint32_t*)(oh + (rowbase + r0 + 8) * DMODEL + cc) = hh;
        *(uint32_t*)(ol + (rowbase + r0 + 8) * DMODEL + cc) = ll;
    }
}

// ---------------------------------------------------------------------------
// Launcher
// ---------------------------------------------------------------------------
extern "C" void kernel_launch(void* const* d_in, const int* in_sizes, int n_in,
                              void* d_out, int out_size)
{
    const float* x    = (const float*)d_in[0];
    const float* Wqkv = (const float*)d_in[1];
    const float* bqkv = (const float*)d_in[2];
    const float* Wout = (const float*)d_in[3];
    const float* bout = (const float*)d_in[4];
    float* out = (float*)d_out;

    __half *xh, *xl, *wqh, *wql, *woh, *wol, *qh, *qlp, *ah, *al;
    cudaGetSymbolAddress((void**)&xh,  g_x_h);
    cudaGetSymbolAddress((void**)&xl,  g_x_l);
    cudaGetSymbolAddress((void**)&wqh, g_wqkvT_h);
    cudaGetSymbolAddress((void**)&wql, g_wqkvT_l);
    cudaGetSymbolAddress((void**)&woh, g_woutT_h);
    cudaGetSymbolAddress((void**)&wol, g_woutT_l);
    cudaGetSymbolAddress((void**)&qh,  g_qkv_h);
    cudaGetSymbolAddress((void**)&qlp, g_qkv_l);
    cudaGetSymbolAddress((void**)&ah,  g_att_h);
    cudaGetSymbolAddress((void**)&al,  g_att_l);

    cudaFuncSetAttribute(gemm_h2_kernel<true>,
                         cudaFuncAttributeMaxDynamicSharedMemorySize, 3 * G_BUF);
    cudaFuncSetAttribute(gemm_h2_kernel<false>,
                         cudaFuncAttributeMaxDynamicSharedMemorySize, 3 * G_BUF);
    cudaFuncSetAttribute(attn_h2_kernel,
                         cudaFuncAttributeMaxDynamicSharedMemorySize, ATT_SMEM);

    // 0) pre-split x; transpose+split weights
    split_kernel<<<(MROWS * DMODEL / 4 + 255) / 256, 256>>>(x, xh, xl,
                                                            MROWS * DMODEL / 4);
    transpose_split_kernel<<<dim3(D3 / 32, DMODEL / 32), 256>>>(Wqkv, wqh, wql,
                                                                DMODEL, D3);
    transpose_split_kernel<<<dim3(DMODEL / 32, DMODEL / 32), 256>>>(Wout, woh, wol,
                                                                    DMODEL, DMODEL);

    // 1) QKV projection -> split halves
    {
        dim3 grid(D3 / 128, MROWS / 128);
        gemm_h2_kernel<true><<<grid, 128, 3 * G_BUF>>>(
            xh, xl, wqh, wql, bqkv, nullptr, qh, qlp, MROWS, D3, DMODEL);
    }
    // 2) Attention -> split halves
    {
        dim3 grid(NTOK / 128, NH, BB);
        attn_h2_kernel<<<grid, 256, ATT_SMEM>>>(qh, qlp, ah, al);
    }
    // 3) Output projection -> fp32 out
    {
        dim3 grid(DMODEL / 128, MROWS / 128);
        gemm_h2_kernel<false><<<grid, 128, 3 * G_BUF>>>(
            ah, al, woh, wol, bout, out, nullptr, nullptr, MROWS, DMODEL, DMODEL);
    }
}

// round 13
// speedup vs baseline: 1.1546x; 1.1546x over previous
#include <cuda_runtime.h>
#include <cuda_fp16.h>
#include <cstdint>
#include <cstddef>

// Problem constants
#define BB     4
#define NTOK   2048
#define DMODEL 1024
#define NH     16
#define HD     64
#define D3     (3 * DMODEL)    // 3072
#define MROWS  (BB * NTOK)     // 8192
#define SCALE  0.125f          // 1/sqrt(64)

// Scratch (static device globals — allocation-free). All operands pre-split
// into fp16 (hi, lo) pairs so hot loops do zero conversion work.
__device__ __half g_x_h[(size_t)MROWS * DMODEL];
__device__ __half g_x_l[(size_t)MROWS * DMODEL];
__device__ __half g_wqkvT_h[(size_t)D3 * DMODEL];
__device__ __half g_wqkvT_l[(size_t)D3 * DMODEL];
__device__ __half g_woutT_h[(size_t)DMODEL * DMODEL];
__device__ __half g_woutT_l[(size_t)DMODEL * DMODEL];
__device__ __half g_qkv_h[(size_t)MROWS * D3];
__device__ __half g_qkv_l[(size_t)MROWS * D3];
__device__ __half g_att_h[(size_t)MROWS * DMODEL];
__device__ __half g_att_l[(size_t)MROWS * DMODEL];

// ---------------------------------------------------------------------------
// Helpers (sm_80-era PTX only: mma.sync / ldmatrix / cp.async)
// ---------------------------------------------------------------------------
__device__ __forceinline__ void split2(float a, float b, uint32_t& hi, uint32_t& lo) {
    __half2 h = __floats2half2_rn(a, b);
    float2 hf = __half22float2(h);
    __half2 l = __floats2half2_rn(a - hf.x, b - hf.y);
    hi = *reinterpret_cast<uint32_t*>(&h);
    lo = *reinterpret_cast<uint32_t*>(&l);
}
__device__ __forceinline__ uint32_t smem_u32(const void* p) {
    uint32_t a;
    asm("{ .reg .u64 t; cvta.to.shared.u64 t, %1; cvt.u32.u64 %0, t; }"
        : "=r"(a) : "l"(p));
    return a;
}
__device__ __forceinline__ void cp16(uint32_t dst, const void* src) {
    asm volatile("cp.async.cg.shared.global [%0], [%1], 16;"
                 :: "r"(dst), "l"(src));
}
#define CP_COMMIT() asm volatile("cp.async.commit_group;" ::: "memory")
#define CP_WAIT0()  asm volatile("cp.async.wait_group 0;" ::: "memory")
#define CP_WAIT1()  asm volatile("cp.async.wait_group 1;" ::: "memory")

#define MMA_F16(d, a0, a1, a2, a3, b0, b1)                                     \
    asm volatile(                                                              \
        "mma.sync.aligned.m16n8k16.row.col.f32.f16.f16.f32 "                   \
        "{%0,%1,%2,%3},{%4,%5,%6,%7},{%8,%9},{%0,%1,%2,%3};"                   \
        : "+f"((d)[0]), "+f"((d)[1]), "+f"((d)[2]), "+f"((d)[3])               \
        : "r"(a0), "r"(a1), "r"(a2), "r"(a3), "r"(b0), "r"(b1))

#define LDSM_X4(R0, R1, R2, R3, ADDR)                                          \
    asm volatile("ldmatrix.sync.aligned.m8n8.x4.shared.b16 {%0,%1,%2,%3},[%4];"\
                 : "=r"(R0), "=r"(R1), "=r"(R2), "=r"(R3) : "r"(ADDR))
#define LDSM_X4T(R0, R1, R2, R3, ADDR)                                         \
    asm volatile("ldmatrix.sync.aligned.m8n8.x4.trans.shared.b16 "             \
                 "{%0,%1,%2,%3},[%4];"                                         \
                 : "=r"(R0), "=r"(R1), "=r"(R2), "=r"(R3) : "r"(ADDR))

// ---------------------------------------------------------------------------
// Pre-pass kernels
// ---------------------------------------------------------------------------
__global__ __launch_bounds__(256) void split_kernel(
    const float* __restrict__ in, __half* __restrict__ oh,
    __half* __restrict__ ol, int n4)
{
    int i = blockIdx.x * 256 + threadIdx.x;
    if (i >= n4) return;
    float4 v = *(const float4*)(in + (size_t)i * 4);
    uint32_t h0, l0, h1, l1;
    split2(v.x, v.y, h0, l0);
    split2(v.z, v.w, h1, l1);
    *(uint2*)(oh + (size_t)i * 4) = make_uint2(h0, h1);
    *(uint2*)(ol + (size_t)i * 4) = make_uint2(l0, l1);
}

// out[C][R] = split(in[R][C])
__global__ __launch_bounds__(256) void transpose_split_kernel(
    const float* __restrict__ in, __half* __restrict__ oh,
    __half* __restrict__ ol, int R, int Cc)
{
    __shared__ float tile[32][33];
    int c0 = blockIdx.x * 32, r0 = blockIdx.y * 32;
    int lx = threadIdx.x & 31, ly = threadIdx.x >> 5;
#pragma unroll
    for (int rr = ly; rr < 32; rr += 8)
        tile[rr][lx] = in[(size_t)(r0 + rr) * Cc + c0 + lx];
    __syncthreads();
#pragma unroll
    for (int rr = ly; rr < 32; rr += 8) {
        float v = tile[lx][rr];
        __half h = __float2half_rn(v);
        __half l = __float2half_rn(v - __half2float(h));
        oh[(size_t)(c0 + rr) * R + r0 + lx] = h;
        ol[(size_t)(c0 + rr) * R + r0 + lx] = l;
    }
}

// ---------------------------------------------------------------------------
// fp16x3 GEMM (pre-split operands): C = A@BT^T + bias
// BM=128, BN=128, BK=32 halves; 256 threads (8 warps 4x2); warp tile 32x64
// (the measured-best shape: 16 warps/SM). 3-stage cp.async pipeline;
// __launch_bounds__(256,2) keeps 2 CTAs/SM. B-fragments double-buffered
// through the p-loop so B LDSM latency hides under the previous p's MMAs.
// Smem rows: 32 halves = 4 chunks x 16B, chunk XOR (row&3). ldmatrix frags.
// ---------------------------------------------------------------------------
#define G_BUF 32768   // bytes per pipeline stage (4 regions x 8KB)

template<bool SPLIT_OUT>
__global__ __launch_bounds__(256, 2) void gemm_h2_kernel(
    const __half* __restrict__ Ah, const __half* __restrict__ Al,
    const __half* __restrict__ Bh, const __half* __restrict__ Bl,
    const float* __restrict__ bias,
    float* __restrict__ Cf, __half* __restrict__ Ch, __half* __restrict__ Cl,
    int M, int Nn, int K)
{
    extern __shared__ char smc[];
    const uint32_t sb = smem_u32(smc);

    const int t    = threadIdx.x;
    const int lane = t & 31, wid = t >> 5;
    const int g    = lane >> 2, tg = lane & 3;
    const int wm   = wid >> 1, wn = wid & 1;
    const int m0   = blockIdx.y * 128;
    const int n0   = blockIdx.x * 128;

    // gmem->smem mapping: per region, thread covers row t>>1, chunks 2(t&1),2(t&1)+1
    const int ldrow = t >> 1;
    const int ldc0  = (t & 1) * 2;
    const __half* __restrict__ arrs[4] = {Ah, Al, Bh, Bl};
    const int rowb[4] = {m0, m0, n0, n0};

    // ldmatrix address components (region-relative)
    const int arow[2] = {wm * 32 + (lane & 15), wm * 32 + 16 + (lane & 15)};
    const int acb = lane >> 4;
    const int brow[4] = {
        wn * 64 + 0  + ((lane >> 4) << 3) + (lane & 7),
        wn * 64 + 16 + ((lane >> 4) << 3) + (lane & 7),
        wn * 64 + 32 + ((lane >> 4) << 3) + (lane & 7),
        wn * 64 + 48 + ((lane >> 4) << 3) + (lane & 7)};
    const int bcb = (lane >> 3) & 1;

    float acc[2][8][4];
#pragma unroll
    for (int mt = 0; mt < 2; mt++)
#pragma unroll
        for (int nt = 0; nt < 8; nt++)
#pragma unroll
            for (int i = 0; i < 4; i++) acc[mt][nt][i] = 0.0f;

    const int NT = K / 32;

    auto issue = [&](int kt, int ss) {
#pragma unroll
        for (int r = 0; r < 4; r++) {
#pragma unroll
            for (int j = 0; j < 2; j++) {
                int ch = ldc0 + j;
                const __half* src = arrs[r] +
                    (size_t)(rowb[r] + ldrow) * K + kt * 32 + ch * 8;
                uint32_t dst = sb + ss * G_BUF + r * 8192 +
                    (ldrow * 4 + (ch ^ (ldrow & 3))) * 16;
                cp16(dst, src);
            }
        }
        CP_COMMIT();
    };

    issue(0, 0);
    issue(1, 1);

    int stage = 0;
    for (int kt = 0; kt < NT; kt++) {
        if (kt + 1 < NT) CP_WAIT1(); else CP_WAIT0();
        __syncthreads();
        if (kt + 2 < NT) {
            int ns = stage + 2; if (ns >= 3) ns -= 3;
            issue(kt + 2, ns);
        }

        const uint32_t bufb = sb + stage * G_BUF;
#pragma unroll
        for (int kc = 0; kc < 2; kc++) {
            // A fragments for this kc-half
            uint32_t ah[2][4], al[2][4];
#pragma unroll
            for (int mt = 0; mt < 2; mt++) {
                int ch = kc * 2 + acb;
                uint32_t ad = bufb + (arow[mt] * 4 + (ch ^ (arow[mt] & 3))) * 16;
                LDSM_X4(ah[mt][0], ah[mt][1], ah[mt][2], ah[mt][3], ad);
                LDSM_X4(al[mt][0], al[mt][1], al[mt][2], al[mt][3], ad + 8192);
            }
            // B fragment pipeline: prefetch p=0, then load p+1 under p's MMAs
            const int bch = kc * 2 + bcb;
            uint32_t bhA[4], blA[4], bhB[4], blB[4];
            {
                uint32_t bd = bufb + 16384 +
                    (brow[0] * 4 + (bch ^ (brow[0] & 3))) * 16;
                LDSM_X4(bhA[0], bhA[1], bhA[2], bhA[3], bd);
                LDSM_X4(blA[0], blA[1], blA[2], blA[3], bd + 8192);
            }
#pragma unroll
            for (int p = 0; p < 4; p++) {
                uint32_t* bh = (p & 1) ? bhB : bhA;
                uint32_t* bl = (p & 1) ? blB : blA;
                uint32_t* nh = (p & 1) ? bhA : bhB;
                uint32_t* nl = (p & 1) ? blA : blB;
                if (p < 3) {
                    uint32_t bd = bufb + 16384 +
                        (brow[p + 1] * 4 + (bch ^ (brow[p + 1] & 3))) * 16;
                    LDSM_X4(nh[0], nh[1], nh[2], nh[3], bd);
                    LDSM_X4(nl[0], nl[1], nl[2], nl[3], bd + 8192);
                }
#pragma unroll
                for (int e = 0; e < 2; e++) {
                    uint32_t bh0 = e ? bh[2] : bh[0], bh1 = e ? bh[3] : bh[1];
                    uint32_t bl0 = e ? bl[2] : bl[0], bl1 = e ? bl[3] : bl[1];
#pragma unroll
                    for (int mt = 0; mt < 2; mt++) {
                        float* d = acc[mt][2 * p + e];
                        MMA_F16(d, ah[mt][0], ah[mt][1], ah[mt][2], ah[mt][3], bh0, bh1);
                        MMA_F16(d, ah[mt][0], ah[mt][1], ah[mt][2], ah[mt][3], bl0, bl1);
                        MMA_F16(d, al[mt][0], al[mt][1], al[mt][2], al[mt][3], bh0, bh1);
                    }
                }
            }
        }
        if (++stage == 3) stage = 0;
    }

    // epilogue
#pragma unroll
    for (int mt = 0; mt < 2; mt++) {
        int r0 = m0 + wm * 32 + mt * 16 + g;
#pragma unroll
        for (int nt = 0; nt < 8; nt++) {
            int cc = n0 + wn * 64 + nt * 8 + tg * 2;
            float2 bv = *(const float2*)(bias + cc);
            float* d = acc[mt][nt];
            float v0 = d[0] + bv.x, v1 = d[1] + bv.y;
            float v2 = d[2] + bv.x, v3 = d[3] + bv.y;
            if (SPLIT_OUT) {
                uint32_t h, l;
                split2(v0, v1, h, l);
                *(uint32_t*)(Ch + (size_t)r0 * Nn + cc) = h;
                *(uint32_t*)(Cl + (size_t)r0 * Nn + cc) = l;
                split2(v2, v3, h, l);
                *(uint32_t*)(Ch + (size_t)(r0 + 8) * Nn + cc) = h;
                *(uint32_t*)(Cl + (size_t)(r0 + 8) * Nn + cc) = l;
            } else {
                *(float2*)(Cf + (size_t)r0 * Nn + cc) = make_float2(v0, v1);
                *(float2*)(Cf + (size_t)(r0 + 8) * Nn + cc) = make_float2(v2, v3);
            }
        }
    }
}

// ---------------------------------------------------------------------------
// Flash attention, fp16x3, pre-split inputs, ldmatrix fragments.
// CTA = 128 q-rows x one (b,h); 8 warps, each 16 q-rows. K/V double-buffered.
// One barrier per tile (top-of-loop sync covers buffer reuse).
// Smem rows: 64 halves = 8 chunks x 16B, chunk XOR (row&7).
// Layout: Qh 0 | Ql 16K | buf0 {Kh,Kl,Vh,Vl @8K} 32K | buf1 64K. Total 96K.
// ---------------------------------------------------------------------------
#define ATT_SMEM 98304
#define AKV_BASE 32768

__global__ __launch_bounds__(256) void attn_h2_kernel(
    const __half* __restrict__ qh, const __half* __restrict__ ql,
    __half* __restrict__ oh, __half* __restrict__ ol)
{
    extern __shared__ char smc[];
    const uint32_t sb = smem_u32(smc);

    const int t    = threadIdx.x;
    const int lane = t & 31, wid = t >> 5;
    const int g    = lane >> 2, tg = lane & 3;
    const int q0   = blockIdx.x * 128;
    const int h    = blockIdx.y;
    const int b    = blockIdx.z;
    const size_t rowbase = (size_t)b * NTOK;

    // ldmatrix row components
    const int qrow = wid * 16 + (lane & 15);
    const int qcb  = lane >> 4;
    const int krow[4] = {
        0  + ((lane >> 4) << 3) + (lane & 7),
        16 + ((lane >> 4) << 3) + (lane & 7),
        32 + ((lane >> 4) << 3) + (lane & 7),
        48 + ((lane >> 4) << 3) + (lane & 7)};
    const int kcb = (lane >> 3) & 1;
    const int vrow[2] = {
        ( (lane >> 4)      ) * 16 + (((lane >> 3) & 1) << 3) + (lane & 7),
        ( (lane >> 4) + 2  ) * 16 + (((lane >> 3) & 1) << 3) + (lane & 7)};

    // ---- issue Q (16 cp/thread) + KV tile 0 (committed together) ----
    {
#pragma unroll
        for (int hl = 0; hl < 2; hl++) {
            const __half* arr = hl ? ql : qh;
#pragma unroll
            for (int j = 0; j < 4; j++) {
                int id = t * 4 + j, row = id >> 3, ch = id & 7;
                const __half* src = arr + (rowbase + q0 + row) * D3 + h * 64 + ch * 8;
                uint32_t dst = sb + hl * 16384 + (row * 8 + (ch ^ (row & 7))) * 16;
                cp16(dst, src);
            }
        }
    }
    auto issue_kv = [&](int kt, int bb) {
        const int k0 = kt * 64;
#pragma unroll
        for (int r = 0; r < 4; r++) {
            const __half* arr = (r & 1) ? ql : qh;
            const int colb = ((r >> 1) ? 2 * DMODEL : DMODEL) + h * 64;
#pragma unroll
            for (int j = 0; j < 2; j++) {
                int id = t * 2 + j, row = id >> 3, ch = id & 7;
                const __half* src = arr + (rowbase + k0 + row) * D3 + colb + ch * 8;
                uint32_t dst = sb + AKV_BASE + bb * 32768 + r * 8192 +
                               (row * 8 + (ch ^ (row & 7))) * 16;
                cp16(dst, src);
            }
        }
        CP_COMMIT();
    };
    issue_kv(0, 0);

    float m0f = -1e30f, m1f = -1e30f, l0 = 0.0f, l1 = 0.0f;
    float oacc[8][4];
#pragma unroll
    for (int nt = 0; nt < 8; nt++)
#pragma unroll
        for (int i = 0; i < 4; i++) oacc[nt][i] = 0.0f;

    for (int kt = 0; kt < NTOK / 64; kt++) {
        const int bb = kt & 1;
        CP_WAIT0();
        __syncthreads();
        if (kt + 1 < NTOK / 64) issue_kv(kt + 1, bb ^ 1);

        const uint32_t kvb = sb + AKV_BASE + bb * 32768;

        // ---- S = Q K^T (3-term) ----
        float sacc[8][4];
#pragma unroll
        for (int nt = 0; nt < 8; nt++)
#pragma unroll
            for (int i = 0; i < 4; i++) sacc[nt][i] = 0.0f;

#pragma unroll
        for (int ks = 0; ks < 4; ks++) {
            int qch = ks * 2 + qcb;
            uint32_t qa = sb + (qrow * 8 + (qch ^ (qrow & 7))) * 16;
            uint32_t Qh_[4], Ql_[4];
            LDSM_X4(Qh_[0], Qh_[1], Qh_[2], Qh_[3], qa);
            LDSM_X4(Ql_[0], Ql_[1], Ql_[2], Ql_[3], qa + 16384);
#pragma unroll
            for (int p = 0; p < 4; p++) {
                int kch = ks * 2 + kcb;
                uint32_t ka = kvb + (krow[p] * 8 + (kch ^ (krow[p] & 7))) * 16;
                uint32_t Kh_[4], Kl_[4];
                LDSM_X4(Kh_[0], Kh_[1], Kh_[2], Kh_[3], ka);
                LDSM_X4(Kl_[0], Kl_[1], Kl_[2], Kl_[3], ka + 8192);
#pragma unroll
                for (int e = 0; e < 2; e++) {
                    uint32_t bh0 = e ? Kh_[2] : Kh_[0], bh1 = e ? Kh_[3] : Kh_[1];
                    uint32_t bl0 = e ? Kl_[2] : Kl_[0], bl1 = e ? Kl_[3] : Kl_[1];
                    float* d = sacc[2 * p + e];
                    MMA_F16(d, Qh_[0], Qh_[1], Qh_[2], Qh_[3], bh0, bh1);
                    MMA_F16(d, Qh_[0], Qh_[1], Qh_[2], Qh_[3], bl0, bl1);
                    MMA_F16(d, Ql_[0], Ql_[1], Ql_[2], Ql_[3], bh0, bh1);
                }
            }
        }

        // ---- online softmax ----
        float mx0 = -1e30f, mx1 = -1e30f;
#pragma unroll
        for (int nt = 0; nt < 8; nt++) {
            sacc[nt][0] *= SCALE; sacc[nt][1] *= SCALE;
            sacc[nt][2] *= SCALE; sacc[nt][3] *= SCALE;
            mx0 = fmaxf(mx0, fmaxf(sacc[nt][0], sacc[nt][1]));
            mx1 = fmaxf(mx1, fmaxf(sacc[nt][2], sacc[nt][3]));
        }
        mx0 = fmaxf(mx0, __shfl_xor_sync(0xffffffffu, mx0, 1));
        mx0 = fmaxf(mx0, __shfl_xor_sync(0xffffffffu, mx0, 2));
        mx1 = fmaxf(mx1, __shfl_xor_sync(0xffffffffu, mx1, 1));
        mx1 = fmaxf(mx1, __shfl_xor_sync(0xffffffffu, mx1, 2));
        float mn0 = fmaxf(m0f, mx0), mn1 = fmaxf(m1f, mx1);
        float c0 = __expf(m0f - mn0), c1 = __expf(m1f - mn1);
        m0f = mn0; m1f = mn1;
        float s0 = 0.0f, s1 = 0.0f;
#pragma unroll
        for (int nt = 0; nt < 8; nt++) {
            sacc[nt][0] = __expf(sacc[nt][0] - mn0);
            sacc[nt][1] = __expf(sacc[nt][1] - mn0);
            sacc[nt][2] = __expf(sacc[nt][2] - mn1);
            sacc[nt][3] = __expf(sacc[nt][3] - mn1);
            s0 += sacc[nt][0] + sacc[nt][1];
            s1 += sacc[nt][2] + sacc[nt][3];
        }
        s0 += __shfl_xor_sync(0xffffffffu, s0, 1);
        s0 += __shfl_xor_sync(0xffffffffu, s0, 2);
        s1 += __shfl_xor_sync(0xffffffffu, s1, 1);
        s1 += __shfl_xor_sync(0xffffffffu, s1, 2);
        l0 = l0 * c0 + s0;
        l1 = l1 * c1 + s1;
#pragma unroll
        for (int nt = 0; nt < 8; nt++) {
            oacc[nt][0] *= c0; oacc[nt][1] *= c0;
            oacc[nt][2] *= c1; oacc[nt][3] *= c1;
        }

        // ---- P fragments (registers; S C-frag == PV A-frag layout) ----
        uint32_t ph[4][4], pl[4][4];
#pragma unroll
        for (int s = 0; s < 4; s++) {
            split2(sacc[2 * s][0],     sacc[2 * s][1],     ph[s][0], pl[s][0]);
            split2(sacc[2 * s][2],     sacc[2 * s][3],     ph[s][1], pl[s][1]);
            split2(sacc[2 * s + 1][0], sacc[2 * s + 1][1], ph[s][2], pl[s][2]);
            split2(sacc[2 * s + 1][2], sacc[2 * s + 1][3], ph[s][3], pl[s][3]);
        }

        // ---- O += P V (3-term); V B-frags via ldmatrix.trans ----
#pragma unroll
        for (int nt = 0; nt < 8; nt++) {
            uint32_t vh[2][4], vl[2][4];
#pragma unroll
            for (int sg = 0; sg < 2; sg++) {
                uint32_t va = kvb + 16384 +
                    (vrow[sg] * 8 + (nt ^ (vrow[sg] & 7))) * 16;
                LDSM_X4T(vh[sg][0], vh[sg][1], vh[sg][2], vh[sg][3], va);
                LDSM_X4T(vl[sg][0], vl[sg][1], vl[sg][2], vl[sg][3], va + 8192);
            }
            float* d = oacc[nt];
#pragma unroll
            for (int s = 0; s < 4; s++) {
                int sg = s >> 1, o = (s & 1) * 2;
                MMA_F16(d, ph[s][0], ph[s][1], ph[s][2], ph[s][3],
                        vh[sg][o], vh[sg][o + 1]);
                MMA_F16(d, ph[s][0], ph[s][1], ph[s][2], ph[s][3],
                        vl[sg][o], vl[sg][o + 1]);
                MMA_F16(d, pl[s][0], pl[s][1], pl[s][2], pl[s][3],
                        vh[sg][o], vh[sg][o + 1]);
            }
        }
    }

    // ---- epilogue: normalize, split to hi/lo halves ----
    float inv0 = 1.0f / l0, inv1 = 1.0f / l1;
    int r0 = q0 + wid * 16 + g;
#pragma unroll
    for (int nt = 0; nt < 8; nt++) {
        int cc = h * HD + nt * 8 + tg * 2;
        uint32_t hh, ll;
        split2(oacc[nt][0] * inv0, oacc[nt][1] * inv0, hh, ll);
        *(uint32_t*)(oh + (rowbase + r0) * DMODEL + cc) = hh;
        *(uint32_t*)(ol + (rowbase + r0) * DMODEL + cc) = ll;
        split2(oacc[nt][2] * inv1, oacc[nt][3] * inv1, hh, ll);
        *(uint32_t*)(oh + (rowbase + r0 + 8) * DMODEL + cc) = hh;
        *(uint32_t*)(ol + (rowbase + r0 + 8) * DMODEL + cc) = ll;
    }
}

// ---------------------------------------------------------------------------
// Launcher
// ---------------------------------------------------------------------------
extern "C" void kernel_launch(void* const* d_in, const int* in_sizes, int n_in,
                              void* d_out, int out_size)
{
    const float* x    = (const float*)d_in[0];
    const float* Wqkv = (const float*)d_in[1];
    const float* bqkv = (const float*)d_in[2];
    const float* Wout = (const float*)d_in[3];
    const float* bout = (const float*)d_in[4];
    float* out = (float*)d_out;

    __half *xh, *xl, *wqh, *wql, *woh, *wol, *qh, *qlp, *ah, *al;
    cudaGetSymbolAddress((void**)&xh,  g_x_h);
    cudaGetSymbolAddress((void**)&xl,  g_x_l);
    cudaGetSymbolAddress((void**)&wqh, g_wqkvT_h);
    cudaGetSymbolAddress((void**)&wql, g_wqkvT_l);
    cudaGetSymbolAddress((void**)&woh, g_woutT_h);
    cudaGetSymbolAddress((void**)&wol, g_woutT_l);
    cudaGetSymbolAddress((void**)&qh,  g_qkv_h);
    cudaGetSymbolAddress((void**)&qlp, g_qkv_l);
    cudaGetSymbolAddress((void**)&ah,  g_att_h);
    cudaGetSymbolAddress((void**)&al,  g_att_l);

    cudaFuncSetAttribute(gemm_h2_kernel<true>,
                         cudaFuncAttributeMaxDynamicSharedMemorySize, 3 * G_BUF);
    cudaFuncSetAttribute(gemm_h2_kernel<false>,
                         cudaFuncAttributeMaxDynamicSharedMemorySize, 3 * G_BUF);
    cudaFuncSetAttribute(attn_h2_kernel,
                         cudaFuncAttributeMaxDynamicSharedMemorySize, ATT_SMEM);

    // 0) pre-split x; transpose+split weights
    split_kernel<<<(MROWS * DMODEL / 4 + 255) / 256, 256>>>(x, xh, xl,
                                                            MROWS * DMODEL / 4);
    transpose_split_kernel<<<dim3(D3 / 32, DMODEL / 32), 256>>>(Wqkv, wqh, wql,
                                                                DMODEL, D3);
    transpose_split_kernel<<<dim3(DMODEL / 32, DMODEL / 32), 256>>>(Wout, woh, wol,
                                                                    DMODEL, DMODEL);

    // 1) QKV projection -> split halves
    {
        dim3 grid(D3 / 128, MROWS / 128);
        gemm_h2_kernel<true><<<grid, 256, 3 * G_BUF>>>(
            xh, xl, wqh, wql, bqkv, nullptr, qh, qlp, MROWS, D3, DMODEL);
    }
    // 2) Attention -> split halves
    {
        dim3 grid(NTOK / 128, NH, BB);
        attn_h2_kernel<<<grid, 256, ATT_SMEM>>>(qh, qlp, ah, al);
    }
    // 3) Output projection -> fp32 out
    {
        dim3 grid(DMODEL / 128, MROWS / 128);
        gemm_h2_kernel<false><<<grid, 256, 3 * G_BUF>>>(
            ah, al, woh, wol, bout, out, nullptr, nullptr, MROWS, DMODEL, DMODEL);
    }
}